// round 9
// baseline (speedup 1.0000x reference)
#include <cuda_runtime.h>
#include <cuda_bf16.h>
#include <cstdint>

// ---------------------------------------------------------------------------
// b=16, c=512, hw=4096
//   inter = sigmoid(depth @ rgb^T)    (512x512, K=4096, NT)
//   out   = rgb + inter @ depth       (512x4096, K=512; B via ldsm.trans)
// mma.sync bf16 3-pass split precision, fp32 accum.
// BK=32, 4 stages, single-sync multistage pipeline, SW64 swizzle (64B rows).
// ---------------------------------------------------------------------------

#define BATCH 16
#define CDIM  512
#define HW    4096

#define BM 128
#define BN 128
#define BK 32

#define OFF_AHI 0
#define OFF_ALO 8192
#define OFF_BHI 16384
#define OFF_BLO 24576
#define STAGE   32768
#define NSTAGE  4
#define SMEM_TOTAL (NSTAGE * STAGE)   // 128 KB per CTA

// ---------------------------------------------------------------------------
// Scratch (__device__ globals; allocation-guard-safe)
// ---------------------------------------------------------------------------
__device__ __align__(128) __nv_bfloat16 g_depth_hi[BATCH * CDIM * HW];   // [b,c,s]
__device__ __align__(128) __nv_bfloat16 g_depth_lo[BATCH * CDIM * HW];
__device__ __align__(128) __nv_bfloat16 g_rgb_hi  [BATCH * CDIM * HW];   // [b,c,s]
__device__ __align__(128) __nv_bfloat16 g_rgb_lo  [BATCH * CDIM * HW];
__device__ __align__(128) __nv_bfloat16 g_inter_hi[BATCH * CDIM * CDIM]; // [b,c,d]
__device__ __align__(128) __nv_bfloat16 g_inter_lo[BATCH * CDIM * CDIM];

// ---------------------------------------------------------------------------
// PTX helpers (sm_80-era; compile under plain compute_103)
// ---------------------------------------------------------------------------
__device__ __forceinline__ uint32_t smem_u32(const void* p) {
    uint32_t a;
    asm("{ .reg .u64 t; cvta.to.shared.u64 t, %1; cvt.u32.u64 %0, t; }"
        : "=r"(a) : "l"(p));
    return a;
}

__device__ __forceinline__ void cpasync16(uint32_t s, const void* g) {
    asm volatile("cp.async.cg.shared.global [%0], [%1], 16;" :: "r"(s), "l"(g));
}
#define CP_COMMIT() asm volatile("cp.async.commit_group;" ::: "memory")
#define CP_WAIT2()  asm volatile("cp.async.wait_group 2;" ::: "memory")

__device__ __forceinline__ void ldsm4(uint32_t (&r)[4], uint32_t a) {
    asm volatile("ldmatrix.sync.aligned.m8n8.x4.shared.b16 {%0,%1,%2,%3}, [%4];"
                 : "=r"(r[0]), "=r"(r[1]), "=r"(r[2]), "=r"(r[3]) : "r"(a));
}
__device__ __forceinline__ void ldsm4t(uint32_t (&r)[4], uint32_t a) {
    asm volatile("ldmatrix.sync.aligned.m8n8.x4.trans.shared.b16 {%0,%1,%2,%3}, [%4];"
                 : "=r"(r[0]), "=r"(r[1]), "=r"(r[2]), "=r"(r[3]) : "r"(a));
}

__device__ __forceinline__ void mma16816(float (&d)[4], const uint32_t (&a)[4],
                                         uint32_t b0, uint32_t b1) {
    asm volatile(
        "mma.sync.aligned.m16n8k16.row.col.f32.bf16.bf16.f32 "
        "{%0,%1,%2,%3},{%4,%5,%6,%7},{%8,%9},{%0,%1,%2,%3};"
        : "+f"(d[0]), "+f"(d[1]), "+f"(d[2]), "+f"(d[3])
        : "r"(a[0]), "r"(a[1]), "r"(a[2]), "r"(a[3]), "r"(b0), "r"(b1));
}

// SW64 swizzle for 64-byte rows: XOR bits[4:5] with bits[7:8].
__device__ __forceinline__ uint32_t sw(uint32_t off) {
    return off ^ ((off >> 3) & 0x30);
}

// ---------------------------------------------------------------------------
// Producer: one stage. A: BMx32 (m-major, 64B rows).  B:
//   !TRANSB: BNx32 n-major (64B rows), same addressing as A.
//   TRANSB : 32xBN k-major source (depth straight); 4 subtiles of
//            32(k) x 32(n), 64B rows, sw() within each subtile.
// 512 16B-chunks per tile; 256 threads x 2 chunks.
// ---------------------------------------------------------------------------
template <bool TRANSB>
__device__ __forceinline__ void produce(
    uint32_t sb, int stage,
    const __nv_bfloat16* __restrict__ Ahi, const __nv_bfloat16* __restrict__ Alo,
    const __nv_bfloat16* __restrict__ Bhi, const __nv_bfloat16* __restrict__ Blo,
    int lda, int ldb, int kcol)
{
    const int tid = threadIdx.x;
    const uint32_t s0 = sb + stage * STAGE;
#pragma unroll
    for (int i = 0; i < 2; ++i) {
        const int id = tid + 256 * i;
        // A tile
        {
            const int row = id >> 2, c = id & 3;
            const uint32_t off = sw((uint32_t)row * 64u + (uint32_t)c * 16u);
            const size_t ga = (size_t)row * lda + kcol + c * 8;
            cpasync16(s0 + OFF_AHI + off, Ahi + ga);
            cpasync16(s0 + OFF_ALO + off, Alo + ga);
        }
        // B tile
        if (!TRANSB) {
            const int row = id >> 2, c = id & 3;
            const uint32_t off = sw((uint32_t)row * 64u + (uint32_t)c * 16u);
            const size_t gb = (size_t)row * ldb + kcol + c * 8;
            cpasync16(s0 + OFF_BHI + off, Bhi + gb);
            cpasync16(s0 + OFF_BLO + off, Blo + gb);
        } else {
            const int h = id >> 7, k = (id >> 2) & 31, cn = id & 3;
            const uint32_t off = (uint32_t)h * 2048u +
                                 sw((uint32_t)k * 64u + (uint32_t)cn * 16u);
            const size_t gb = (size_t)(kcol + k) * ldb + h * 32 + cn * 8;
            cpasync16(s0 + OFF_BHI + off, Bhi + gb);
            cpasync16(s0 + OFF_BLO + off, Blo + gb);
        }
    }
    CP_COMMIT();
}

// ---------------------------------------------------------------------------
// Consumer: one stage = 2 k16 steps, 3-pass split MMA.
// 8 warps as 2(m) x 4(n); warp tile 64x32. acc[t:4 m16][nidx:4 n8][4].
// ---------------------------------------------------------------------------
template <bool TRANSB>
__device__ __forceinline__ void consume(uint32_t sb, int stage,
                                        float (&acc)[4][4][4]) {
    const int tid = threadIdx.x;
    const int lane = tid & 31, wid = tid >> 5;
    const int wm = wid >> 2, wn = wid & 3;
    const uint32_t s0 = sb + stage * STAGE;

    const int a_r = lane & 15, a_c = lane >> 4;
    const int b_n = ((lane >> 4) << 3) + (lane & 7);
    const int b_c = (lane >> 3) & 1;
    const int bt_k = ((lane >> 3) & 1) * 8 + (lane & 7);
    const int bt_u = lane >> 4;

#pragma unroll
    for (int kk = 0; kk < 2; ++kk) {
        uint32_t bh[2][4], bl[2][4];
#pragma unroll
        for (int u = 0; u < 2; ++u) {
            if (!TRANSB) {
                const uint32_t off =
                    sw((uint32_t)(wn * 32 + u * 16 + b_n) * 64u +
                       (uint32_t)(kk * 2 + b_c) * 16u);
                ldsm4(bh[u], s0 + OFF_BHI + off);
                ldsm4(bl[u], s0 + OFF_BLO + off);
            } else {
                const uint32_t off = (uint32_t)wn * 2048u +
                    sw((uint32_t)(kk * 16 + bt_k) * 64u +
                       (uint32_t)(u * 2 + bt_u) * 16u);
                ldsm4t(bh[u], s0 + OFF_BHI + off);
                ldsm4t(bl[u], s0 + OFF_BLO + off);
            }
        }
#pragma unroll
        for (int t = 0; t < 4; ++t) {
            uint32_t ah[4], al[4];
            const uint32_t off =
                sw((uint32_t)(wm * 64 + t * 16 + a_r) * 64u +
                   (uint32_t)(kk * 2 + a_c) * 16u);
            ldsm4(ah, s0 + OFF_AHI + off);
            ldsm4(al, s0 + OFF_ALO + off);
#pragma unroll
            for (int u = 0; u < 2; ++u) {
#pragma unroll
                for (int h = 0; h < 2; ++h) {
                    float (&d)[4] = acc[t][u * 2 + h];
                    mma16816(d, ah, bh[u][h * 2], bh[u][h * 2 + 1]);
                    mma16816(d, ah, bl[u][h * 2], bl[u][h * 2 + 1]);
                    mma16816(d, al, bh[u][h * 2], bh[u][h * 2 + 1]);
                }
            }
        }
    }
}

// ---------------------------------------------------------------------------
// Multistage mainloop: ONE __syncthreads per chunk; produce (chunk c+3) is
// issued right after the sync (overwrites stage (c-1)%4, drained by the sync)
// and before consume(c), overlapping loads with the full chunk's MMA work.
// Group math: 3 primed commits + 1/iter (empty at tail) => wait_group 2
// guarantees chunk c has landed at iteration c.
// ---------------------------------------------------------------------------
template <bool TRANSB>
__device__ __forceinline__ void mainloop(
    uint32_t sb, float (&acc)[4][4][4],
    const __nv_bfloat16* Ahi, const __nv_bfloat16* Alo,
    const __nv_bfloat16* Bhi, const __nv_bfloat16* Blo,
    int lda, int ldb, int nch)
{
#pragma unroll
    for (int t = 0; t < 4; ++t)
#pragma unroll
        for (int n = 0; n < 4; ++n)
#pragma unroll
            for (int r = 0; r < 4; ++r) acc[t][n][r] = 0.0f;

#pragma unroll
    for (int cc = 0; cc < NSTAGE - 1; ++cc) {
        if (cc < nch)
            produce<TRANSB>(sb, cc, Ahi, Alo, Bhi, Blo, lda, ldb, cc * BK);
        else
            CP_COMMIT();
    }
    for (int c = 0; c < nch; ++c) {
        CP_WAIT2();
        __syncthreads();
        const int pc = c + NSTAGE - 1;
        if (pc < nch)
            produce<TRANSB>(sb, pc % NSTAGE, Ahi, Alo, Bhi, Blo, lda, ldb,
                            pc * BK);
        else
            CP_COMMIT();
        consume<TRANSB>(sb, c % NSTAGE, acc);
    }
}

__device__ __forceinline__ float sigmoidf(float x) {
    return 1.0f / (1.0f + __expf(-x));
}

// ---------------------------------------------------------------------------
// GEMM1: inter = sigmoid(depth @ rgb^T); epilogue splits to bf16 hi/lo
// grid (4, 4, 16), 256 threads
// ---------------------------------------------------------------------------
__global__ __launch_bounds__(256)
void gemm1_tc() {
    extern __shared__ char smem[];
    const uint32_t sb = smem_u32(smem);
    const int b = blockIdx.z;
    const size_t aoff = ((size_t)b * CDIM + blockIdx.y * BM) * HW;
    const size_t boff = ((size_t)b * CDIM + blockIdx.x * BN) * HW;

    float acc[4][4][4];
    mainloop<false>(sb, acc, g_depth_hi + aoff, g_depth_lo + aoff,
                    g_rgb_hi + boff, g_rgb_lo + boff, HW, HW, HW / BK);

    const int lane = threadIdx.x & 31, wid = threadIdx.x >> 5;
    const int wm = wid >> 2, wn = wid & 3;
    const int r0 = blockIdx.y * BM + wm * 64 + (lane >> 2);
    const int c0 = blockIdx.x * BN + wn * 32 + (lane & 3) * 2;
    __nv_bfloat16* ih = g_inter_hi + (size_t)b * CDIM * CDIM;
    __nv_bfloat16* il = g_inter_lo + (size_t)b * CDIM * CDIM;
#pragma unroll
    for (int t = 0; t < 4; ++t) {
#pragma unroll
        for (int nidx = 0; nidx < 4; ++nidx) {
            const int n = c0 + nidx * 8;
#pragma unroll
            for (int half = 0; half < 2; ++half) {
                const int m = r0 + t * 16 + half * 8;
                const float v0 = sigmoidf(acc[t][nidx][half * 2 + 0]);
                const float v1 = sigmoidf(acc[t][nidx][half * 2 + 1]);
                const __nv_bfloat16 h0 = __float2bfloat16(v0);
                const __nv_bfloat16 h1 = __float2bfloat16(v1);
                const __nv_bfloat16 l0 = __float2bfloat16(v0 - __bfloat162float(h0));
                const __nv_bfloat16 l1 = __float2bfloat16(v1 - __bfloat162float(h1));
                const size_t idx = (size_t)m * CDIM + n;
                *(__nv_bfloat162*)(ih + idx) = __nv_bfloat162(h0, h1);
                *(__nv_bfloat162*)(il + idx) = __nv_bfloat162(l0, l1);
            }
        }
    }
}

// ---------------------------------------------------------------------------
// GEMM2: out = rgb + inter @ depth (B via ldsm.trans on straight layout)
// grid (32, 4, 16), 256 threads
// ---------------------------------------------------------------------------
__global__ __launch_bounds__(256)
void gemm2_tc(const float* __restrict__ rgb, float* __restrict__ out) {
    extern __shared__ char smem[];
    const uint32_t sb = smem_u32(smem);
    const int b = blockIdx.z;
    const size_t aoff = ((size_t)b * CDIM + blockIdx.y * BM) * CDIM;
    const size_t boff = (size_t)b * CDIM * HW + blockIdx.x * BN;

    float acc[4][4][4];
    mainloop<true>(sb, acc, g_inter_hi + aoff, g_inter_lo + aoff,
                   g_depth_hi + boff, g_depth_lo + boff, CDIM, HW, CDIM / BK);

    const int lane = threadIdx.x & 31, wid = threadIdx.x >> 5;
    const int wm = wid >> 2, wn = wid & 3;
    const int r0 = blockIdx.y * BM + wm * 64 + (lane >> 2);
    const int c0 = blockIdx.x * BN + wn * 32 + (lane & 3) * 2;
    const size_t base = (size_t)b * CDIM * HW;
#pragma unroll
    for (int t = 0; t < 4; ++t) {
#pragma unroll
        for (int nidx = 0; nidx < 4; ++nidx) {
            const int n = c0 + nidx * 8;
#pragma unroll
            for (int half = 0; half < 2; ++half) {
                const int m = r0 + t * 16 + half * 8;
                const size_t idx = base + (size_t)m * HW + n;
                const float2 rv = *(const float2*)(rgb + idx);
                float2 v;
                v.x = acc[t][nidx][half * 2 + 0] + rv.x;
                v.y = acc[t][nidx][half * 2 + 1] + rv.y;
                *(float2*)(out + idx) = v;
            }
        }
    }
}

// ---------------------------------------------------------------------------
// Split both inputs: fp32 -> bf16 hi/lo, 8 elems/thread each
// ---------------------------------------------------------------------------
__global__ __launch_bounds__(256)
void split_kernel(const float* __restrict__ rgb, const float* __restrict__ depth) {
    const size_t i = ((size_t)blockIdx.x * 256 + threadIdx.x) * 8;
#pragma unroll
    for (int which = 0; which < 2; ++which) {
        const float* src = which ? depth : rgb;
        __nv_bfloat16* dh = which ? g_depth_hi : g_rgb_hi;
        __nv_bfloat16* dl = which ? g_depth_lo : g_rgb_lo;
        float4 a = *(const float4*)(src + i);
        float4 c = *(const float4*)(src + i + 4);
        float v[8] = {a.x, a.y, a.z, a.w, c.x, c.y, c.z, c.w};
        union { __nv_bfloat16 h[8]; uint4 u; } H, L;
#pragma unroll
        for (int j = 0; j < 8; ++j) {
            __nv_bfloat16 hb = __float2bfloat16(v[j]);
            H.h[j] = hb;
            L.h[j] = __float2bfloat16(v[j] - __bfloat162float(hb));
        }
        *(uint4*)(dh + i) = H.u;
        *(uint4*)(dl + i) = L.u;
    }
}

// ---------------------------------------------------------------------------
// Launch
// ---------------------------------------------------------------------------
extern "C" void kernel_launch(void* const* d_in, const int* in_sizes, int n_in,
                              void* d_out, int out_size) {
    const float* rgb   = (const float*)d_in[0];
    const float* depth = (const float*)d_in[1];
    float* out = (float*)d_out;

    cudaFuncSetAttribute(gemm1_tc,
                         cudaFuncAttributeMaxDynamicSharedMemorySize, SMEM_TOTAL);
    cudaFuncSetAttribute(gemm2_tc,
                         cudaFuncAttributeMaxDynamicSharedMemorySize, SMEM_TOTAL);

    const size_t TOT = (size_t)BATCH * CDIM * HW;   // 33,554,432
    split_kernel<<<(unsigned)(TOT / 8 / 256), 256>>>(rgb, depth);

    gemm1_tc<<<dim3(CDIM / BN, CDIM / BM, BATCH), 256, SMEM_TOTAL>>>();
    gemm2_tc<<<dim3(HW / BN, CDIM / BM, BATCH), 256, SMEM_TOTAL>>>(rgb, out);
}

// round 11
// speedup vs baseline: 1.0770x; 1.0770x over previous
#include <cuda_runtime.h>
#include <cuda_bf16.h>
#include <cstdint>

// ---------------------------------------------------------------------------
// b=16, c=512, hw=4096
//   inter = sigmoid(depth @ rgb^T)    (512x512, K=4096, NT)
//   out   = rgb + inter @ depth       (512x4096, K=512; B via ldsm.trans)
// mma.sync bf16 3-pass split precision, fp32 accum.
// BK=32, 4 stages, one sync/chunk (produce after consume), register
// double-buffered fragments, SW64 swizzle (64B rows).
// ---------------------------------------------------------------------------

#define BATCH 16
#define CDIM  512
#define HW    4096

#define BM 128
#define BN 128
#define BK 32

#define OFF_AHI 0
#define OFF_ALO 8192
#define OFF_BHI 16384
#define OFF_BLO 24576
#define STAGE   32768
#define NSTAGE  4
#define SMEM_TOTAL (NSTAGE * STAGE)   // 128 KB per CTA

// ---------------------------------------------------------------------------
// Scratch (__device__ globals; allocation-guard-safe)
// ---------------------------------------------------------------------------
__device__ __align__(128) __nv_bfloat16 g_depth_hi[BATCH * CDIM * HW];   // [b,c,s]
__device__ __align__(128) __nv_bfloat16 g_depth_lo[BATCH * CDIM * HW];
__device__ __align__(128) __nv_bfloat16 g_rgb_hi  [BATCH * CDIM * HW];   // [b,c,s]
__device__ __align__(128) __nv_bfloat16 g_rgb_lo  [BATCH * CDIM * HW];
__device__ __align__(128) __nv_bfloat16 g_inter_hi[BATCH * CDIM * CDIM]; // [b,c,d]
__device__ __align__(128) __nv_bfloat16 g_inter_lo[BATCH * CDIM * CDIM];

// ---------------------------------------------------------------------------
// PTX helpers (sm_80-era; compile under plain compute_103)
// ---------------------------------------------------------------------------
__device__ __forceinline__ uint32_t smem_u32(const void* p) {
    uint32_t a;
    asm("{ .reg .u64 t; cvta.to.shared.u64 t, %1; cvt.u32.u64 %0, t; }"
        : "=r"(a) : "l"(p));
    return a;
}

__device__ __forceinline__ void cpasync16(uint32_t s, const void* g) {
    asm volatile("cp.async.cg.shared.global [%0], [%1], 16;" :: "r"(s), "l"(g));
}
#define CP_COMMIT() asm volatile("cp.async.commit_group;" ::: "memory")
#define CP_WAIT2()  asm volatile("cp.async.wait_group 2;" ::: "memory")

__device__ __forceinline__ void ldsm4(uint32_t (&r)[4], uint32_t a) {
    asm volatile("ldmatrix.sync.aligned.m8n8.x4.shared.b16 {%0,%1,%2,%3}, [%4];"
                 : "=r"(r[0]), "=r"(r[1]), "=r"(r[2]), "=r"(r[3]) : "r"(a));
}
__device__ __forceinline__ void ldsm4t(uint32_t (&r)[4], uint32_t a) {
    asm volatile("ldmatrix.sync.aligned.m8n8.x4.trans.shared.b16 {%0,%1,%2,%3}, [%4];"
                 : "=r"(r[0]), "=r"(r[1]), "=r"(r[2]), "=r"(r[3]) : "r"(a));
}

__device__ __forceinline__ void mma16816(float (&d)[4], const uint32_t (&a)[4],
                                         uint32_t b0, uint32_t b1) {
    asm volatile(
        "mma.sync.aligned.m16n8k16.row.col.f32.bf16.bf16.f32 "
        "{%0,%1,%2,%3},{%4,%5,%6,%7},{%8,%9},{%0,%1,%2,%3};"
        : "+f"(d[0]), "+f"(d[1]), "+f"(d[2]), "+f"(d[3])
        : "r"(a[0]), "r"(a[1]), "r"(a[2]), "r"(a[3]), "r"(b0), "r"(b1));
}

// SW64 swizzle for 64-byte rows: XOR bits[4:5] with bits[7:8].
__device__ __forceinline__ uint32_t sw(uint32_t off) {
    return off ^ ((off >> 3) & 0x30);
}

// ---------------------------------------------------------------------------
// Producer: one stage. A: BMx32 (m-major, 64B rows).  B:
//   !TRANSB: BNx32 n-major (64B rows), same addressing as A.
//   TRANSB : 32xBN k-major source (depth straight); 4 subtiles of
//            32(k) x 32(n), 64B rows, sw() within each subtile.
// 512 16B-chunks per tile; 256 threads x 2 chunks.
// ---------------------------------------------------------------------------
template <bool TRANSB>
__device__ __forceinline__ void produce(
    uint32_t sb, int stage,
    const __nv_bfloat16* __restrict__ Ahi, const __nv_bfloat16* __restrict__ Alo,
    const __nv_bfloat16* __restrict__ Bhi, const __nv_bfloat16* __restrict__ Blo,
    int lda, int ldb, int kcol)
{
    const int tid = threadIdx.x;
    const uint32_t s0 = sb + stage * STAGE;
#pragma unroll
    for (int i = 0; i < 2; ++i) {
        const int id = tid + 256 * i;
        // A tile
        {
            const int row = id >> 2, c = id & 3;
            const uint32_t off = sw((uint32_t)row * 64u + (uint32_t)c * 16u);
            const size_t ga = (size_t)row * lda + kcol + c * 8;
            cpasync16(s0 + OFF_AHI + off, Ahi + ga);
            cpasync16(s0 + OFF_ALO + off, Alo + ga);
        }
        // B tile
        if (!TRANSB) {
            const int row = id >> 2, c = id & 3;
            const uint32_t off = sw((uint32_t)row * 64u + (uint32_t)c * 16u);
            const size_t gb = (size_t)row * ldb + kcol + c * 8;
            cpasync16(s0 + OFF_BHI + off, Bhi + gb);
            cpasync16(s0 + OFF_BLO + off, Blo + gb);
        } else {
            const int h = id >> 7, k = (id >> 2) & 31, cn = id & 3;
            const uint32_t off = (uint32_t)h * 2048u +
                                 sw((uint32_t)k * 64u + (uint32_t)cn * 16u);
            const size_t gb = (size_t)(kcol + k) * ldb + h * 32 + cn * 8;
            cpasync16(s0 + OFF_BHI + off, Bhi + gb);
            cpasync16(s0 + OFF_BLO + off, Blo + gb);
        }
    }
    CP_COMMIT();
}

// ---------------------------------------------------------------------------
// Fragment loads for one k16 step (kk in {0,1}) of a stage.
// A: 8 ldsm.x4 (4 m16 tiles, hi+lo).  B: 4 ldsm.x4 (2 n16 groups, hi+lo).
// ---------------------------------------------------------------------------
__device__ __forceinline__ void load_a_frags(uint32_t s0, int kk, int wm,
                                             int a_r, int a_c,
                                             uint32_t (&ah)[4][4],
                                             uint32_t (&al)[4][4]) {
#pragma unroll
    for (int t = 0; t < 4; ++t) {
        const uint32_t off = sw((uint32_t)(wm * 64 + t * 16 + a_r) * 64u +
                                (uint32_t)(kk * 2 + a_c) * 16u);
        ldsm4(ah[t], s0 + OFF_AHI + off);
        ldsm4(al[t], s0 + OFF_ALO + off);
    }
}

template <bool TRANSB>
__device__ __forceinline__ void load_b_frags(uint32_t s0, int kk, int wn,
                                             int b_n, int b_c, int bt_k, int bt_u,
                                             uint32_t (&bh)[2][4],
                                             uint32_t (&bl)[2][4]) {
#pragma unroll
    for (int u = 0; u < 2; ++u) {
        if (!TRANSB) {
            const uint32_t off = sw((uint32_t)(wn * 32 + u * 16 + b_n) * 64u +
                                    (uint32_t)(kk * 2 + b_c) * 16u);
            ldsm4(bh[u], s0 + OFF_BHI + off);
            ldsm4(bl[u], s0 + OFF_BLO + off);
        } else {
            const uint32_t off = (uint32_t)wn * 2048u +
                sw((uint32_t)(kk * 16 + bt_k) * 64u +
                   (uint32_t)(u * 2 + bt_u) * 16u);
            ldsm4t(bh[u], s0 + OFF_BHI + off);
            ldsm4t(bl[u], s0 + OFF_BLO + off);
        }
    }
}

__device__ __forceinline__ void mma_block(float (&acc)[4][4][4],
                                          const uint32_t (&ah)[4][4],
                                          const uint32_t (&al)[4][4],
                                          const uint32_t (&bh)[2][4],
                                          const uint32_t (&bl)[2][4]) {
    // Pass-major order: for each pass, 16 independent accumulator chains.
#pragma unroll
    for (int t = 0; t < 4; ++t)
#pragma unroll
        for (int u = 0; u < 2; ++u)
#pragma unroll
            for (int h = 0; h < 2; ++h)
                mma16816(acc[t][u * 2 + h], ah[t], bh[u][h * 2], bh[u][h * 2 + 1]);
#pragma unroll
    for (int t = 0; t < 4; ++t)
#pragma unroll
        for (int u = 0; u < 2; ++u)
#pragma unroll
            for (int h = 0; h < 2; ++h)
                mma16816(acc[t][u * 2 + h], ah[t], bl[u][h * 2], bl[u][h * 2 + 1]);
#pragma unroll
    for (int t = 0; t < 4; ++t)
#pragma unroll
        for (int u = 0; u < 2; ++u)
#pragma unroll
            for (int h = 0; h < 2; ++h)
                mma16816(acc[t][u * 2 + h], al[t], bh[u][h * 2], bh[u][h * 2 + 1]);
}

// ---------------------------------------------------------------------------
// Consumer: one stage = 2 k16 steps, register double-buffered fragments:
// frags(kk+1) are loaded before the MMA block of kk.
// ---------------------------------------------------------------------------
template <bool TRANSB>
__device__ __forceinline__ void consume(uint32_t sb, int stage,
                                        float (&acc)[4][4][4]) {
    const int tid = threadIdx.x;
    const int lane = tid & 31, wid = tid >> 5;
    const int wm = wid >> 2, wn = wid & 3;
    const uint32_t s0 = sb + stage * STAGE;

    const int a_r = lane & 15, a_c = lane >> 4;
    const int b_n = ((lane >> 4) << 3) + (lane & 7);
    const int b_c = (lane >> 3) & 1;
    const int bt_k = ((lane >> 3) & 1) * 8 + (lane & 7);
    const int bt_u = lane >> 4;

    uint32_t ah[2][4][4], al[2][4][4], bh[2][2][4], bl[2][2][4];

    load_b_frags<TRANSB>(s0, 0, wn, b_n, b_c, bt_k, bt_u, bh[0], bl[0]);
    load_a_frags(s0, 0, wm, a_r, a_c, ah[0], al[0]);

    // kk = 0: prefetch kk=1 frags, then MMA on kk=0 frags
    load_b_frags<TRANSB>(s0, 1, wn, b_n, b_c, bt_k, bt_u, bh[1], bl[1]);
    load_a_frags(s0, 1, wm, a_r, a_c, ah[1], al[1]);
    mma_block(acc, ah[0], al[0], bh[0], bl[0]);
    // kk = 1
    mma_block(acc, ah[1], al[1], bh[1], bl[1]);
}

// ---------------------------------------------------------------------------
// Multistage mainloop: ONE __syncthreads per chunk.  produce(c+3) comes AFTER
// consume(c); it writes stage (c+3)%4 == (c-1)%4, whose consumption by all
// warps was ordered before this iteration's __syncthreads.
// Groups: 3 primed + 1/iter (empty at tail) => wait_group 2 at iter c
// guarantees chunk c has landed.
// ---------------------------------------------------------------------------
template <bool TRANSB>
__device__ __forceinline__ void mainloop(
    uint32_t sb, float (&acc)[4][4][4],
    const __nv_bfloat16* Ahi, const __nv_bfloat16* Alo,
    const __nv_bfloat16* Bhi, const __nv_bfloat16* Blo,
    int lda, int ldb, int nch)
{
#pragma unroll
    for (int t = 0; t < 4; ++t)
#pragma unroll
        for (int n = 0; n < 4; ++n)
#pragma unroll
            for (int r = 0; r < 4; ++r) acc[t][n][r] = 0.0f;

#pragma unroll
    for (int cc = 0; cc < NSTAGE - 1; ++cc) {
        if (cc < nch)
            produce<TRANSB>(sb, cc, Ahi, Alo, Bhi, Blo, lda, ldb, cc * BK);
        else
            CP_COMMIT();
    }
    for (int c = 0; c < nch; ++c) {
        CP_WAIT2();
        __syncthreads();
        consume<TRANSB>(sb, c % NSTAGE, acc);
        const int pc = c + NSTAGE - 1;
        if (pc < nch)
            produce<TRANSB>(sb, pc % NSTAGE, Ahi, Alo, Bhi, Blo, lda, ldb,
                            pc * BK);
        else
            CP_COMMIT();
    }
}

__device__ __forceinline__ float sigmoidf(float x) {
    return 1.0f / (1.0f + __expf(-x));
}

// ---------------------------------------------------------------------------
// GEMM1: inter = sigmoid(depth @ rgb^T); epilogue splits to bf16 hi/lo
// grid (4, 4, 16), 256 threads
// ---------------------------------------------------------------------------
__global__ __launch_bounds__(256)
void gemm1_tc() {
    extern __shared__ char smem[];
    const uint32_t sb = smem_u32(smem);
    const int b = blockIdx.z;
    const size_t aoff = ((size_t)b * CDIM + blockIdx.y * BM) * HW;
    const size_t boff = ((size_t)b * CDIM + blockIdx.x * BN) * HW;

    float acc[4][4][4];
    mainloop<false>(sb, acc, g_depth_hi + aoff, g_depth_lo + aoff,
                    g_rgb_hi + boff, g_rgb_lo + boff, HW, HW, HW / BK);

    const int lane = threadIdx.x & 31, wid = threadIdx.x >> 5;
    const int wm = wid >> 2, wn = wid & 3;
    const int r0 = blockIdx.y * BM + wm * 64 + (lane >> 2);
    const int c0 = blockIdx.x * BN + wn * 32 + (lane & 3) * 2;
    __nv_bfloat16* ih = g_inter_hi + (size_t)b * CDIM * CDIM;
    __nv_bfloat16* il = g_inter_lo + (size_t)b * CDIM * CDIM;
#pragma unroll
    for (int t = 0; t < 4; ++t) {
#pragma unroll
        for (int nidx = 0; nidx < 4; ++nidx) {
            const int n = c0 + nidx * 8;
#pragma unroll
            for (int half = 0; half < 2; ++half) {
                const int m = r0 + t * 16 + half * 8;
                const float v0 = sigmoidf(acc[t][nidx][half * 2 + 0]);
                const float v1 = sigmoidf(acc[t][nidx][half * 2 + 1]);
                const __nv_bfloat16 h0 = __float2bfloat16(v0);
                const __nv_bfloat16 h1 = __float2bfloat16(v1);
                const __nv_bfloat16 l0 = __float2bfloat16(v0 - __bfloat162float(h0));
                const __nv_bfloat16 l1 = __float2bfloat16(v1 - __bfloat162float(h1));
                const size_t idx = (size_t)m * CDIM + n;
                *(__nv_bfloat162*)(ih + idx) = __nv_bfloat162(h0, h1);
                *(__nv_bfloat162*)(il + idx) = __nv_bfloat162(l0, l1);
            }
        }
    }
}

// ---------------------------------------------------------------------------
// GEMM2: out = rgb + inter @ depth (B via ldsm.trans on straight layout)
// grid (32, 4, 16), 256 threads
// ---------------------------------------------------------------------------
__global__ __launch_bounds__(256)
void gemm2_tc(const float* __restrict__ rgb, float* __restrict__ out) {
    extern __shared__ char smem[];
    const uint32_t sb = smem_u32(smem);
    const int b = blockIdx.z;
    const size_t aoff = ((size_t)b * CDIM + blockIdx.y * BM) * CDIM;
    const size_t boff = (size_t)b * CDIM * HW + blockIdx.x * BN;

    float acc[4][4][4];
    mainloop<true>(sb, acc, g_inter_hi + aoff, g_inter_lo + aoff,
                   g_depth_hi + boff, g_depth_lo + boff, CDIM, HW, CDIM / BK);

    const int lane = threadIdx.x & 31, wid = threadIdx.x >> 5;
    const int wm = wid >> 2, wn = wid & 3;
    const int r0 = blockIdx.y * BM + wm * 64 + (lane >> 2);
    const int c0 = blockIdx.x * BN + wn * 32 + (lane & 3) * 2;
    const size_t base = (size_t)b * CDIM * HW;
#pragma unroll
    for (int t = 0; t < 4; ++t) {
#pragma unroll
        for (int nidx = 0; nidx < 4; ++nidx) {
            const int n = c0 + nidx * 8;
#pragma unroll
            for (int half = 0; half < 2; ++half) {
                const int m = r0 + t * 16 + half * 8;
                const size_t idx = base + (size_t)m * HW + n;
                const float2 rv = *(const float2*)(rgb + idx);
                float2 v;
                v.x = acc[t][nidx][half * 2 + 0] + rv.x;
                v.y = acc[t][nidx][half * 2 + 1] + rv.y;
                *(float2*)(out + idx) = v;
            }
        }
    }
}

// ---------------------------------------------------------------------------
// Split both inputs: fp32 -> bf16 hi/lo, 8 elems/thread each
// ---------------------------------------------------------------------------
__global__ __launch_bounds__(256)
void split_kernel(const float* __restrict__ rgb, const float* __restrict__ depth) {
    const size_t i = ((size_t)blockIdx.x * 256 + threadIdx.x) * 8;
#pragma unroll
    for (int which = 0; which < 2; ++which) {
        const float* src = which ? depth : rgb;
        __nv_bfloat16* dh = which ? g_depth_hi : g_rgb_hi;
        __nv_bfloat16* dl = which ? g_depth_lo : g_rgb_lo;
        float4 a = *(const float4*)(src + i);
        float4 c = *(const float4*)(src + i + 4);
        float v[8] = {a.x, a.y, a.z, a.w, c.x, c.y, c.z, c.w};
        union { __nv_bfloat16 h[8]; uint4 u; } H, L;
#pragma unroll
        for (int j = 0; j < 8; ++j) {
            __nv_bfloat16 hb = __float2bfloat16(v[j]);
            H.h[j] = hb;
            L.h[j] = __float2bfloat16(v[j] - __bfloat162float(hb));
        }
        *(uint4*)(dh + i) = H.u;
        *(uint4*)(dl + i) = L.u;
    }
}

// ---------------------------------------------------------------------------
// Launch
// ---------------------------------------------------------------------------
extern "C" void kernel_launch(void* const* d_in, const int* in_sizes, int n_in,
                              void* d_out, int out_size) {
    const float* rgb   = (const float*)d_in[0];
    const float* depth = (const float*)d_in[1];
    float* out = (float*)d_out;

    cudaFuncSetAttribute(gemm1_tc,
                         cudaFuncAttributeMaxDynamicSharedMemorySize, SMEM_TOTAL);
    cudaFuncSetAttribute(gemm2_tc,
                         cudaFuncAttributeMaxDynamicSharedMemorySize, SMEM_TOTAL);

    const size_t TOT = (size_t)BATCH * CDIM * HW;   // 33,554,432
    split_kernel<<<(unsigned)(TOT / 8 / 256), 256>>>(rgb, depth);

    gemm1_tc<<<dim3(CDIM / BN, CDIM / BM, BATCH), 256, SMEM_TOTAL>>>();
    gemm2_tc<<<dim3(HW / BN, CDIM / BM, BATCH), 256, SMEM_TOTAL>>>(rgb, out);
}

// round 12
// speedup vs baseline: 1.3023x; 1.2092x over previous
#include <cuda_runtime.h>
#include <cuda_fp16.h>
#include <cstdint>

// ---------------------------------------------------------------------------
// b=16, c=512, hw=4096
//   inter = sigmoid(depth @ rgb^T)    (512x512, K=4096, NT, 3-pass fp16 split)
//   out   = rgb + inter @ depth       (512x4096, K=512; B via ldsm.trans,
//                                      2-pass: inter_h16 x (depth_hi+depth_lo))
// mma.sync f16, fp32 accum.  BK=32, 3 stages, SW64 swizzle (64B rows).
// ---------------------------------------------------------------------------

#define BATCH 16
#define CDIM  512
#define HW    4096

#define BM 128
#define BN 128
#define BK 32

#define OFF_AHI 0
#define OFF_ALO 8192
#define OFF_BHI 16384
#define OFF_BLO 24576
#define STAGE   32768
#define NSTAGE  3
#define SMEM_TOTAL (NSTAGE * STAGE)   // 96 KB per CTA

// ---------------------------------------------------------------------------
// Scratch (__device__ globals; allocation-guard-safe), all fp16
// ---------------------------------------------------------------------------
__device__ __align__(128) __half g_depth_hi[BATCH * CDIM * HW];   // [b,c,s]
__device__ __align__(128) __half g_depth_lo[BATCH * CDIM * HW];
__device__ __align__(128) __half g_rgb_hi  [BATCH * CDIM * HW];   // [b,c,s]
__device__ __align__(128) __half g_rgb_lo  [BATCH * CDIM * HW];
__device__ __align__(128) __half g_inter_h [BATCH * CDIM * CDIM]; // [b,c,d]

// ---------------------------------------------------------------------------
// PTX helpers (sm_80-era; compile under plain compute_103)
// ---------------------------------------------------------------------------
__device__ __forceinline__ uint32_t smem_u32(const void* p) {
    uint32_t a;
    asm("{ .reg .u64 t; cvta.to.shared.u64 t, %1; cvt.u32.u64 %0, t; }"
        : "=r"(a) : "l"(p));
    return a;
}

__device__ __forceinline__ void cpasync16(uint32_t s, const void* g) {
    asm volatile("cp.async.cg.shared.global [%0], [%1], 16;" :: "r"(s), "l"(g));
}
#define CP_COMMIT() asm volatile("cp.async.commit_group;" ::: "memory")
#define CP_WAIT2()  asm volatile("cp.async.wait_group 2;" ::: "memory")

__device__ __forceinline__ void ldsm4(uint32_t (&r)[4], uint32_t a) {
    asm volatile("ldmatrix.sync.aligned.m8n8.x4.shared.b16 {%0,%1,%2,%3}, [%4];"
                 : "=r"(r[0]), "=r"(r[1]), "=r"(r[2]), "=r"(r[3]) : "r"(a));
}
__device__ __forceinline__ void ldsm4t(uint32_t (&r)[4], uint32_t a) {
    asm volatile("ldmatrix.sync.aligned.m8n8.x4.trans.shared.b16 {%0,%1,%2,%3}, [%4];"
                 : "=r"(r[0]), "=r"(r[1]), "=r"(r[2]), "=r"(r[3]) : "r"(a));
}

__device__ __forceinline__ void mma16816(float (&d)[4], const uint32_t (&a)[4],
                                         uint32_t b0, uint32_t b1) {
    asm volatile(
        "mma.sync.aligned.m16n8k16.row.col.f32.f16.f16.f32 "
        "{%0,%1,%2,%3},{%4,%5,%6,%7},{%8,%9},{%0,%1,%2,%3};"
        : "+f"(d[0]), "+f"(d[1]), "+f"(d[2]), "+f"(d[3])
        : "r"(a[0]), "r"(a[1]), "r"(a[2]), "r"(a[3]), "r"(b0), "r"(b1));
}

// SW64 swizzle for 64-byte rows: XOR bits[4:5] with bits[7:8].
__device__ __forceinline__ uint32_t sw(uint32_t off) {
    return off ^ ((off >> 3) & 0x30);
}

// ---------------------------------------------------------------------------
// Producers.  A: BMx32 (m-major, 64B rows).  B:
//   MODE 0 (GEMM1): B = BNx32 n-major (64B rows); A hi+lo, B hi+lo.
//   MODE 1 (GEMM2): B = 32xBN k-major source via 4 subtiles of 32(k)x32(n);
//                   A hi ONLY, B hi+lo.
// ---------------------------------------------------------------------------
template <int MODE>
__device__ __forceinline__ void produce(
    uint32_t sb, int stage,
    const __half* __restrict__ Ahi, const __half* __restrict__ Alo,
    const __half* __restrict__ Bhi, const __half* __restrict__ Blo,
    int lda, int ldb, int kcol)
{
    const int tid = threadIdx.x;
    const uint32_t s0 = sb + stage * STAGE;
#pragma unroll
    for (int i = 0; i < 2; ++i) {
        const int id = tid + 256 * i;
        // A tile(s)
        {
            const int row = id >> 2, c = id & 3;
            const uint32_t off = sw((uint32_t)row * 64u + (uint32_t)c * 16u);
            const size_t ga = (size_t)row * lda + kcol + c * 8;
            cpasync16(s0 + OFF_AHI + off, Ahi + ga);
            if (MODE == 0)
                cpasync16(s0 + OFF_ALO + off, Alo + ga);
        }
        // B tiles (hi+lo)
        if (MODE == 0) {
            const int row = id >> 2, c = id & 3;
            const uint32_t off = sw((uint32_t)row * 64u + (uint32_t)c * 16u);
            const size_t gb = (size_t)row * ldb + kcol + c * 8;
            cpasync16(s0 + OFF_BHI + off, Bhi + gb);
            cpasync16(s0 + OFF_BLO + off, Blo + gb);
        } else {
            const int h = id >> 7, k = (id >> 2) & 31, cn = id & 3;
            const uint32_t off = (uint32_t)h * 2048u +
                                 sw((uint32_t)k * 64u + (uint32_t)cn * 16u);
            const size_t gb = (size_t)(kcol + k) * ldb + h * 32 + cn * 8;
            cpasync16(s0 + OFF_BHI + off, Bhi + gb);
            cpasync16(s0 + OFF_BLO + off, Blo + gb);
        }
    }
    CP_COMMIT();
}

// ---------------------------------------------------------------------------
// Consumer: one stage = 2 k16 steps.
// 8 warps as 2(m) x 4(n); warp tile 64x32. acc[t:4 m16][nidx:4 n8][4].
// MODE 0: 3 passes (ah*bh, ah*bl, al*bh).  MODE 1: 2 passes (ah*bh, ah*bl).
// ---------------------------------------------------------------------------
template <int MODE>
__device__ __forceinline__ void consume(uint32_t sb, int stage,
                                        float (&acc)[4][4][4]) {
    const int tid = threadIdx.x;
    const int lane = tid & 31, wid = tid >> 5;
    const int wm = wid >> 2, wn = wid & 3;
    const uint32_t s0 = sb + stage * STAGE;

    const int a_r = lane & 15, a_c = lane >> 4;
    const int b_n = ((lane >> 4) << 3) + (lane & 7);
    const int b_c = (lane >> 3) & 1;
    const int bt_k = ((lane >> 3) & 1) * 8 + (lane & 7);
    const int bt_u = lane >> 4;

#pragma unroll
    for (int kk = 0; kk < 2; ++kk) {
        uint32_t bh[2][4], bl[2][4];
#pragma unroll
        for (int u = 0; u < 2; ++u) {
            if (MODE == 0) {
                const uint32_t off =
                    sw((uint32_t)(wn * 32 + u * 16 + b_n) * 64u +
                       (uint32_t)(kk * 2 + b_c) * 16u);
                ldsm4(bh[u], s0 + OFF_BHI + off);
                ldsm4(bl[u], s0 + OFF_BLO + off);
            } else {
                const uint32_t off = (uint32_t)wn * 2048u +
                    sw((uint32_t)(kk * 16 + bt_k) * 64u +
                       (uint32_t)(u * 2 + bt_u) * 16u);
                ldsm4t(bh[u], s0 + OFF_BHI + off);
                ldsm4t(bl[u], s0 + OFF_BLO + off);
            }
        }
#pragma unroll
        for (int t = 0; t < 4; ++t) {
            uint32_t ah[4], al[4];
            const uint32_t off =
                sw((uint32_t)(wm * 64 + t * 16 + a_r) * 64u +
                   (uint32_t)(kk * 2 + a_c) * 16u);
            ldsm4(ah, s0 + OFF_AHI + off);
            if (MODE == 0)
                ldsm4(al, s0 + OFF_ALO + off);
#pragma unroll
            for (int u = 0; u < 2; ++u) {
#pragma unroll
                for (int h = 0; h < 2; ++h) {
                    float (&d)[4] = acc[t][u * 2 + h];
                    mma16816(d, ah, bh[u][h * 2], bh[u][h * 2 + 1]);
                    mma16816(d, ah, bl[u][h * 2], bl[u][h * 2 + 1]);
                    if (MODE == 0)
                        mma16816(d, al, bh[u][h * 2], bh[u][h * 2 + 1]);
                }
            }
        }
    }
}

// ---------------------------------------------------------------------------
// Multistage mainloop (R8 structure: two syncs/chunk, produce after consume
// into the just-drained stage).  Groups: 3 primed + 1/iter => wait_group 2
// at iter c guarantees chunk c has landed.
// ---------------------------------------------------------------------------
template <int MODE>
__device__ __forceinline__ void mainloop(
    uint32_t sb, float (&acc)[4][4][4],
    const __half* Ahi, const __half* Alo,
    const __half* Bhi, const __half* Blo,
    int lda, int ldb, int nch)
{
#pragma unroll
    for (int t = 0; t < 4; ++t)
#pragma unroll
        for (int n = 0; n < 4; ++n)
#pragma unroll
            for (int r = 0; r < 4; ++r) acc[t][n][r] = 0.0f;

#pragma unroll
    for (int cc = 0; cc < NSTAGE; ++cc) {
        if (cc < nch)
            produce<MODE>(sb, cc, Ahi, Alo, Bhi, Blo, lda, ldb, cc * BK);
        else
            CP_COMMIT();
    }
    for (int c = 0; c < nch; ++c) {
        CP_WAIT2();
        __syncthreads();
        consume<MODE>(sb, c % NSTAGE, acc);
        __syncthreads();
        if (c + NSTAGE < nch)
            produce<MODE>(sb, c % NSTAGE, Ahi, Alo, Bhi, Blo, lda, ldb,
                          (c + NSTAGE) * BK);
        else
            CP_COMMIT();
    }
}

__device__ __forceinline__ float sigmoidf(float x) {
    return 1.0f / (1.0f + __expf(-x));
}

// ---------------------------------------------------------------------------
// GEMM1: inter = sigmoid(depth @ rgb^T); epilogue stores inter_h fp16
// grid (4, 4, 16), 256 threads
// ---------------------------------------------------------------------------
__global__ __launch_bounds__(256, 2)
void gemm1_tc() {
    extern __shared__ char smem[];
    const uint32_t sb = smem_u32(smem);
    const int b = blockIdx.z;
    const size_t aoff = ((size_t)b * CDIM + blockIdx.y * BM) * HW;
    const size_t boff = ((size_t)b * CDIM + blockIdx.x * BN) * HW;

    float acc[4][4][4];
    mainloop<0>(sb, acc, g_depth_hi + aoff, g_depth_lo + aoff,
                g_rgb_hi + boff, g_rgb_lo + boff, HW, HW, HW / BK);

    const int lane = threadIdx.x & 31, wid = threadIdx.x >> 5;
    const int wm = wid >> 2, wn = wid & 3;
    const int r0 = blockIdx.y * BM + wm * 64 + (lane >> 2);
    const int c0 = blockIdx.x * BN + wn * 32 + (lane & 3) * 2;
    __half* ih = g_inter_h + (size_t)b * CDIM * CDIM;
#pragma unroll
    for (int t = 0; t < 4; ++t) {
#pragma unroll
        for (int nidx = 0; nidx < 4; ++nidx) {
            const int n = c0 + nidx * 8;
#pragma unroll
            for (int half2i = 0; half2i < 2; ++half2i) {
                const int m = r0 + t * 16 + half2i * 8;
                const float v0 = sigmoidf(acc[t][nidx][half2i * 2 + 0]);
                const float v1 = sigmoidf(acc[t][nidx][half2i * 2 + 1]);
                const size_t idx = (size_t)m * CDIM + n;
                *(__half2*)(ih + idx) = __floats2half2_rn(v0, v1);
            }
        }
    }
}

// ---------------------------------------------------------------------------
// GEMM2: out = rgb + inter_h @ depth (B via ldsm.trans; 2-pass)
// grid (32, 4, 16), 256 threads
// ---------------------------------------------------------------------------
__global__ __launch_bounds__(256, 2)
void gemm2_tc(const float* __restrict__ rgb, float* __restrict__ out) {
    extern __shared__ char smem[];
    const uint32_t sb = smem_u32(smem);
    const int b = blockIdx.z;
    const size_t aoff = ((size_t)b * CDIM + blockIdx.y * BM) * CDIM;
    const size_t boff = (size_t)b * CDIM * HW + blockIdx.x * BN;

    float acc[4][4][4];
    mainloop<1>(sb, acc, g_inter_h + aoff, (const __half*)nullptr,
                g_depth_hi + boff, g_depth_lo + boff, CDIM, HW, CDIM / BK);

    const int lane = threadIdx.x & 31, wid = threadIdx.x >> 5;
    const int wm = wid >> 2, wn = wid & 3;
    const int r0 = blockIdx.y * BM + wm * 64 + (lane >> 2);
    const int c0 = blockIdx.x * BN + wn * 32 + (lane & 3) * 2;
    const size_t base = (size_t)b * CDIM * HW;
#pragma unroll
    for (int t = 0; t < 4; ++t) {
#pragma unroll
        for (int nidx = 0; nidx < 4; ++nidx) {
            const int n = c0 + nidx * 8;
#pragma unroll
            for (int half2i = 0; half2i < 2; ++half2i) {
                const int m = r0 + t * 16 + half2i * 8;
                const size_t idx = base + (size_t)m * HW + n;
                const float2 rv = *(const float2*)(rgb + idx);
                float2 v;
                v.x = acc[t][nidx][half2i * 2 + 0] + rv.x;
                v.y = acc[t][nidx][half2i * 2 + 1] + rv.y;
                *(float2*)(out + idx) = v;
            }
        }
    }
}

// ---------------------------------------------------------------------------
// Split both inputs: fp32 -> fp16 hi/lo, 8 elems/thread each
// ---------------------------------------------------------------------------
__global__ __launch_bounds__(256)
void split_kernel(const float* __restrict__ rgb, const float* __restrict__ depth) {
    const size_t i = ((size_t)blockIdx.x * 256 + threadIdx.x) * 8;
#pragma unroll
    for (int which = 0; which < 2; ++which) {
        const float* src = which ? depth : rgb;
        __half* dh = which ? g_depth_hi : g_rgb_hi;
        __half* dl = which ? g_depth_lo : g_rgb_lo;
        float4 a = *(const float4*)(src + i);
        float4 c = *(const float4*)(src + i + 4);
        float v[8] = {a.x, a.y, a.z, a.w, c.x, c.y, c.z, c.w};
        union { __half h[8]; uint4 u; } H, L;
#pragma unroll
        for (int j = 0; j < 8; ++j) {
            __half hb = __float2half_rn(v[j]);
            H.h[j] = hb;
            L.h[j] = __float2half_rn(v[j] - __half2float(hb));
        }
        *(uint4*)(dh + i) = H.u;
        *(uint4*)(dl + i) = L.u;
    }
}

// ---------------------------------------------------------------------------
// Launch
// ---------------------------------------------------------------------------
extern "C" void kernel_launch(void* const* d_in, const int* in_sizes, int n_in,
                              void* d_out, int out_size) {
    const float* rgb   = (const float*)d_in[0];
    const float* depth = (const float*)d_in[1];
    float* out = (float*)d_out;

    cudaFuncSetAttribute(gemm1_tc,
                         cudaFuncAttributeMaxDynamicSharedMemorySize, SMEM_TOTAL);
    cudaFuncSetAttribute(gemm2_tc,
                         cudaFuncAttributeMaxDynamicSharedMemorySize, SMEM_TOTAL);

    const size_t TOT = (size_t)BATCH * CDIM * HW;   // 33,554,432
    split_kernel<<<(unsigned)(TOT / 8 / 256), 256>>>(rgb, depth);

    gemm1_tc<<<dim3(CDIM / BN, CDIM / BM, BATCH), 256, SMEM_TOTAL>>>();
    gemm2_tc<<<dim3(HW / BN, CDIM / BM, BATCH), 256, SMEM_TOTAL>>>(rgb, out);
}